// round 5
// baseline (speedup 1.0000x reference)
#include <cuda_runtime.h>
#include <stddef.h>

// ---------------------------------------------------------------------------
// Sparse 3D UNet forward (UNetV2): every layer is a gather-GEMM
//   out[i, :] = sum_k  feat[nbr[i,k], :] @ W[k]      (nbr[i,k] == -1 -> zero)
// fused with BN scale/bias, optional residual-add (pre-ReLU), ReLU, and
// optional post-ReLU channel-pair reduce. Concats are realized by writing
// conv outputs into a stride-128 (or stride-64) "cat" buffer.
//
// R1 fix (unverified; R2-R4 were broker timeouts): __shared__ vector buffers
// must be 16B-aligned. Previously sf/sw landed at a 4 mod 16 smem offset
// after s_idx+s_hit -> float2/float4 smem stores trapped with
// "misaligned address". Resubmitted unchanged to land a clean baseline.
// ---------------------------------------------------------------------------

#define TILE_R 64
#define MAXN   524288   // generous bound on rows at any level

// Scratch (allocation-free: __device__ globals)
__device__ float g_t0 [(size_t)MAXN * 64];
__device__ float g_t1 [(size_t)MAXN * 64];
__device__ float g_cat[(size_t)MAXN * 128];
__device__ float g_x1 [(size_t)131072 * 32];
__device__ float g_x2 [(size_t)MAXN * 32];
__device__ float g_x3 [(size_t)MAXN * 64];

template<int CIN, int COUT>
__global__ __launch_bounds__(128)
void spconv_kernel(const float* __restrict__ fin, int in_stride,
                   float* __restrict__ fout, int out_stride,
                   const int* __restrict__ nbr,
                   const float* __restrict__ Wall,      // [27][CIN][COUT]
                   const float* __restrict__ scale,     // [COUT]
                   const float* __restrict__ bias,      // [COUT]
                   const float* __restrict__ resid, int resid_stride,  // nullable
                   const float* __restrict__ rsum,      // nullable, stride 2*COUT
                   int N)
{
    constexpr int CHUNK  = (CIN < 32) ? CIN : 32;   // ci processed per pass
    constexpr int NCHUNK = CIN / CHUNK;
    constexpr int NC = COUT / 16;                   // cols per thread (2 or 4)
    constexpr int MR = 8;                           // rows per thread
    constexpr int FS = CHUNK + 2;                   // smem feat row stride (bank de-phase)
    constexpr int F2 = CHUNK / 2;                   // float2 per gathered row

    // Vector-accessed smem first, 16B-aligned (R1 alignment fix).
    __shared__ __align__(16) float sf[TILE_R * FS];
    __shared__ __align__(16) float sw[CHUNK * COUT];
    __shared__ int   s_idx[TILE_R * 27];
    __shared__ int   s_hit;

    const int tid   = threadIdx.x;
    const int row0  = blockIdx.x * TILE_R;
    const int tc    = tid & 15;        // 16 column groups
    const int tr    = tid >> 4;        // 8 row groups
    const int rbase = tr * MR;

    if (tid == 0) s_hit = 0;
    __syncthreads();

    // Coalesced load of the 64x27 neighbor tile + build 27-bit hit mask
    int lm = 0;
    for (int i = tid; i < TILE_R * 27; i += 128) {
        int r = i / 27;
        int k = i - r * 27;
        int idx = -1;
        if (row0 + r < N) idx = nbr[(size_t)row0 * 27 + i];
        s_idx[i] = idx;
        if (idx >= 0) lm |= (1 << k);
    }
    if (lm) atomicOr(&s_hit, lm);
    __syncthreads();
    const unsigned hit = (unsigned)s_hit;

    float acc[MR][NC];
    #pragma unroll
    for (int m = 0; m < MR; m++)
        #pragma unroll
        for (int n = 0; n < NC; n++) acc[m][n] = 0.f;

    for (int k = 0; k < 27; k++) {
        if (!((hit >> k) & 1u)) continue;   // whole tile misses this offset
        #pragma unroll 1
        for (int c0 = 0; c0 < NCHUNK; c0++) {
            __syncthreads();
            // Stage W[k] ci-chunk (contiguous) into smem
            const float4* wsrc =
                (const float4*)(Wall + ((size_t)k * CIN + (size_t)c0 * CHUNK) * COUT);
            for (int i = tid; i < CHUNK * COUT / 4; i += 128)
                ((float4*)sw)[i] = wsrc[i];
            // Gather 64 feature rows (chunk columns) into smem
            for (int i = tid; i < TILE_R * F2; i += 128) {
                int r = i / F2;
                int c = i - r * F2;
                int idx = s_idx[r * 27 + k];
                float2 v = make_float2(0.f, 0.f);
                if (idx >= 0)
                    v = *(const float2*)(fin + (size_t)idx * in_stride + c0 * CHUNK + 2 * c);
                *(float2*)(sf + r * FS + 2 * c) = v;
            }
            __syncthreads();
            // Register-tiled FMA: 8 rows x NC cols per thread
            #pragma unroll
            for (int ci = 0; ci < CHUNK; ci++) {
                float wv[NC];
                #pragma unroll
                for (int n = 0; n < NC; n++)
                    wv[n] = sw[ci * COUT + tc * NC + n];
                float fv[MR];
                #pragma unroll
                for (int m = 0; m < MR; m++)
                    fv[m] = sf[(rbase + m) * FS + ci];
                #pragma unroll
                for (int m = 0; m < MR; m++)
                    #pragma unroll
                    for (int n = 0; n < NC; n++)
                        acc[m][n] = fmaf(fv[m], wv[n], acc[m][n]);
            }
        }
    }

    // Fused epilogue: BN affine, (+resid), ReLU, (+pair-reduce)
    #pragma unroll
    for (int m = 0; m < MR; m++) {
        int row = row0 + rbase + m;
        if (row < N) {
            #pragma unroll
            for (int n = 0; n < NC; n++) {
                int co = tc * NC + n;
                float v = fmaf(acc[m][n], scale[co], bias[co]);
                if (resid) v += resid[(size_t)row * resid_stride + co];
                v = fmaxf(v, 0.f);
                if (rsum) {
                    const float* rp = rsum + (size_t)row * (2 * COUT) + 2 * co;
                    v += rp[0] + rp[1];
                }
                fout[(size_t)row * out_stride + co] = v;
            }
        }
    }
}

template<int CIN, int COUT>
static inline void conv(const float* fin, int is, float* fout, int os,
                        const int* nbr, const float* W,
                        const float* sc, const float* bi, int N,
                        const float* resid = nullptr, int rs = 0,
                        const float* rsum = nullptr)
{
    if (N <= 0) return;
    spconv_kernel<CIN, COUT><<<(N + TILE_R - 1) / TILE_R, 128>>>(
        fin, is, fout, os, nbr, W, sc, bi, resid, rs, rsum, N);
}

extern "C" void kernel_launch(void* const* d_in, const int* in_sizes, int n_in,
                              void* d_out, int out_size)
{
    (void)n_in; (void)out_size;
    const float* vf      = (const float*)d_in[0];
    const float* Win     = (const float*)d_in[1];
    const float* W32     = (const float*)d_in[2];
    const float* W64     = (const float*)d_in[3];
    const float* Wd3     = (const float*)d_in[4];
    const float* W6432   = (const float*)d_in[5];
    const float* W12864  = (const float*)d_in[6];
    const float* bn32    = (const float*)d_in[7];
    const float* bn64    = (const float*)d_in[8];
    const int* nbr1  = (const int*)d_in[9];
    const int* nbr2  = (const int*)d_in[10];
    const int* nbr3  = (const int*)d_in[11];
    const int* nbr4  = (const int*)d_in[12];
    const int* nbrd2 = (const int*)d_in[13];
    const int* nbrd3 = (const int*)d_in[14];
    const int* nbrd4 = (const int*)d_in[15];
    const int* nbri4 = (const int*)d_in[16];
    const int* nbri3 = (const int*)d_in[17];
    const int* nbri2 = (const int*)d_in[18];

    const int N1 = in_sizes[9]  / 27;
    const int N2 = in_sizes[10] / 27;
    const int N3 = in_sizes[11] / 27;
    const int N4 = in_sizes[12] / 27;

    float *t0, *t1, *cat, *x1, *x2, *x3;
    cudaGetSymbolAddress((void**)&t0,  g_t0);
    cudaGetSymbolAddress((void**)&t1,  g_t1);
    cudaGetSymbolAddress((void**)&cat, g_cat);
    cudaGetSymbolAddress((void**)&x1,  g_x1);
    cudaGetSymbolAddress((void**)&x2,  g_x2);
    cudaGetSymbolAddress((void**)&x3,  g_x3);

    #define SC32(i) (bn32 + (size_t)(i) * 64)
    #define BI32(i) (bn32 + (size_t)(i) * 64 + 32)
    #define SC64(i) (bn64 + (size_t)(i) * 128)
    #define BI64(i) (bn64 + (size_t)(i) * 128 + 64)
    #define W32K(i)    (W32    + (size_t)(i) * 27 * 32 * 32)
    #define W64K(i)    (W64    + (size_t)(i) * 27 * 64 * 64)
    #define W6432K(i)  (W6432  + (size_t)(i) * 27 * 64 * 32)
    #define W12864K(i) (W12864 + (size_t)(i) * 27 * 128 * 64)

    // --- Encoder ---
    conv<4,32> (vf, 4,  t0, 32, nbr1,  Win,     SC32(0),  BI32(0),  N1);           // x
    conv<32,32>(t0, 32, x1, 32, nbr1,  W32K(0), SC32(1),  BI32(1),  N1);           // x1
    conv<32,32>(x1, 32, t0, 32, nbrd2, W32K(1), SC32(2),  BI32(2),  N2);           // down2
    conv<32,32>(t0, 32, t1, 32, nbr2,  W32K(2), SC32(3),  BI32(3),  N2);
    conv<32,32>(t1, 32, x2, 32, nbr2,  W32K(3), SC32(4),  BI32(4),  N2);           // x2
    conv<32,64>(x2, 32, t0, 64, nbrd3, Wd3,     SC64(0),  BI64(0),  N3);           // down3
    conv<64,64>(t0, 64, t1, 64, nbr3,  W64K(0), SC64(1),  BI64(1),  N3);
    conv<64,64>(t1, 64, x3, 64, nbr3,  W64K(1), SC64(2),  BI64(2),  N3);           // x3
    conv<64,64>(x3, 64, t0, 64, nbrd4, W64K(2), SC64(3),  BI64(3),  N4);           // down4
    conv<64,64>(t0, 64, t1, 64, nbr4,  W64K(3), SC64(4),  BI64(4),  N4);
    conv<64,64>(t1, 64, cat, 128, nbr4, W64K(4), SC64(5), BI64(5),  N4);           // x4 -> cat[:,0:64]

    // --- Level-4 lateral: basic block + cat conv + reduce ---
    conv<64,64>(cat, 128, t0, 64, nbr4, W64K(5), SC64(6), BI64(6),  N4);           // basic a
    conv<64,64>(t0, 64, cat + 64, 128, nbr4, W64K(6), SC64(7), BI64(7), N4,
                cat, 128);                                                         // basic b (+x4) -> cat[:,64:]
    conv<128,64>(cat, 128, t0, 64, nbr4, W12864K(0), SC64(11), BI64(11), N4,
                 nullptr, 0, cat);                                                 // + reduce(cat,64)

    // --- Up to level 3 ---
    conv<64,64>(t0, 64, cat, 128, nbri4, W64K(7), SC64(8), BI64(8),  N3);          // xu4 -> cat[:,0:64]
    conv<64,64>(x3, 64, t1, 64, nbr3, W64K(8), SC64(9),  BI64(9),  N3);            // basic a
    conv<64,64>(t1, 64, cat + 64, 128, nbr3, W64K(9), SC64(10), BI64(10), N3,
                x3, 64);                                                           // basic b (+x3)
    conv<128,64>(cat, 128, t0, 64, nbr3, W12864K(1), SC64(12), BI64(12), N3,
                 nullptr, 0, cat);                                                 // + reduce

    // --- Up to level 2 ---
    conv<64,32>(t0, 64, cat, 64, nbri3, W6432K(0), SC32(11), BI32(11), N2);        // xu3 -> cat[:,0:32]
    conv<32,32>(x2, 32, t1, 32, nbr2, W32K(4), SC32(5), BI32(5), N2);              // basic a
    conv<32,32>(t1, 32, cat + 32, 64, nbr2, W32K(5), SC32(6), BI32(6), N2,
                x2, 32);                                                           // basic b (+x2)
    conv<64,32>(cat, 64, t0, 32, nbr2, W6432K(1), SC32(12), BI32(12), N2,
                nullptr, 0, cat);                                                  // + reduce(cat,32)

    // --- Up to level 1 ---
    conv<32,32>(t0, 32, cat, 64, nbri2, W32K(6), SC32(7), BI32(7), N1);            // xu2 -> cat[:,0:32]
    conv<32,32>(x1, 32, t1, 32, nbr1, W32K(7), SC32(8), BI32(8), N1);              // basic a
    conv<32,32>(t1, 32, cat + 32, 64, nbr1, W32K(8), SC32(9), BI32(9), N1,
                x1, 32);                                                           // basic b (+x1)
    conv<64,32>(cat, 64, t0, 32, nbr1, W6432K(2), SC32(13), BI32(13), N1,
                nullptr, 0, cat);                                                  // + reduce

    // --- Output head ---
    conv<32,32>(t0, 32, (float*)d_out, 32, nbr1, W32K(9), SC32(10), BI32(10), N1);
}